// round 2
// baseline (speedup 1.0000x reference)
#include <cuda_runtime.h>

#define NN   35
#define EDG  (NN*(NN-1))
#define D1   512
#define D2   256
#define D3   128
#define NS2  16
#define ICH2 (D1/NS2)   // 32
#define NS3  16
#define ICH3 (D2/NS3)   // 16

// scratch (no allocations allowed)
__device__ float g_h1[NN*D1];
__device__ float g_h2[NN*D2];
__device__ float g_h3[NN*D3];
__device__ float g_p2[NS2][NN*D2];
__device__ float g_p3[NS3][NN*D3];

// COO is src-major, fully connected, no self-loops:
// edge(s -> n) has id  s*(NN-1) + (s < n ? n-1 : n)
__device__ __forceinline__ int edge_id(int s, int n) {
    return s*(NN-1) + (s < n ? n-1 : n);
}

// ---------------- Layer 1: in_c = 1 ----------------
__global__ void layer1_kernel(const float* __restrict__ x,
                              const float* __restrict__ ea,
                              const float* __restrict__ w,     // [4, D1]
                              const float* __restrict__ b,     // [D1]
                              const float* __restrict__ root,  // [1, D1]
                              const float* __restrict__ bias) {
    int n = blockIdx.x;
    int o = threadIdx.x;          // 0..511
    __shared__ float4 sc[NN-1];
    __shared__ float  sxs[NN-1];
    if (o < NN-1) {
        int k = o;
        int s = k + (k >= n);
        sc[k]  = *reinterpret_cast<const float4*>(ea + edge_id(s, n)*4);
        sxs[k] = x[s];
    }
    __syncthreads();
    float w0 = w[o], w1 = w[D1+o], w2 = w[2*D1+o], w3 = w[3*D1+o];
    float bb = b[o];
    float acc = 0.f;
    #pragma unroll
    for (int k = 0; k < NN-1; k++) {
        float4 c = sc[k];
        float t = fmaf(c.x, w0, fmaf(c.y, w1, fmaf(c.z, w2, fmaf(c.w, w3, bb))));
        acc = fmaf(sxs[k], fmaxf(t, 0.f), acc);
    }
    float v = acc * (1.f/34.f) + x[n]*root[o] + bias[o];
    g_h1[n*D1+o] = fmaxf(v, 0.f);
}

// ---------------- Layer 2 edge/message kernel ----------------
// grid (NN, NS2), 128 threads; each thread owns outputs (o, o+128)
__global__ void l2edge_kernel(const float* __restrict__ ea,
                              const float* __restrict__ w,    // [4, D1*D2]
                              const float* __restrict__ b,    // [D1*D2]
                              const float* __restrict__ root) // [D1, D2]
{
    int n = blockIdx.x;
    int cs = blockIdx.y;
    int tid = threadIdx.x;
    int ibase = cs*ICH2;
    __shared__ float4 sc[NN-1];
    __shared__ float  sx[NN*ICH2];
    if (tid < NN-1) {
        int k = tid, s = k + (k >= n);
        sc[k] = *reinterpret_cast<const float4*>(ea + edge_id(s, n)*4);
    }
    for (int idx = tid; idx < NN*ICH2; idx += 128) {
        int k = idx / ICH2, i = idx % ICH2;
        int s = (k < NN-1) ? (k + (k >= n)) : n;
        sx[idx] = g_h1[s*D1 + ibase + i];
    }
    __syncthreads();

    int o0 = tid, o1 = tid + 128;
    float acc0 = 0.f, acc1 = 0.f, r0 = 0.f, r1 = 0.f;
    for (int i = 0; i < ICH2; i++) {
        int base = (ibase + i)*D2;
        float w00 = w[            base+o0], w10 = w[            base+o1];
        float w01 = w[  D1*D2 +   base+o0], w11 = w[  D1*D2 +   base+o1];
        float w02 = w[2*D1*D2 +   base+o0], w12 = w[2*D1*D2 +   base+o1];
        float w03 = w[3*D1*D2 +   base+o0], w13 = w[3*D1*D2 +   base+o1];
        float b0  = b[base+o0],             b1v = b[base+o1];
        float xn  = sx[(NN-1)*ICH2 + i];
        r0 = fmaf(xn, root[base+o0], r0);
        r1 = fmaf(xn, root[base+o1], r1);
        #pragma unroll
        for (int k = 0; k < NN-1; k++) {
            float4 c = sc[k];
            float xv = sx[k*ICH2 + i];
            float t0 = fmaf(c.x, w00, fmaf(c.y, w01, fmaf(c.z, w02, fmaf(c.w, w03, b0 ))));
            float t1 = fmaf(c.x, w10, fmaf(c.y, w11, fmaf(c.z, w12, fmaf(c.w, w13, b1v))));
            acc0 = fmaf(xv, fmaxf(t0, 0.f), acc0);
            acc1 = fmaf(xv, fmaxf(t1, 0.f), acc1);
        }
    }
    g_p2[cs][n*D2+o0] = acc0*(1.f/34.f) + r0;
    g_p2[cs][n*D2+o1] = acc1*(1.f/34.f) + r1;
}

__global__ void fin2_kernel(const float* __restrict__ bias) {
    int idx = blockIdx.x*blockDim.x + threadIdx.x;
    if (idx >= NN*D2) return;
    float s = 0.f;
    #pragma unroll
    for (int p = 0; p < NS2; p++) s += g_p2[p][idx];
    g_h2[idx] = fmaxf(s + bias[idx % D2], 0.f);
}

// ---------------- Layer 3 edge/message kernel ----------------
// grid (NN, NS3), 128 threads; 1 output per thread
__global__ void l3edge_kernel(const float* __restrict__ ea,
                              const float* __restrict__ w,    // [4, D2*D3]
                              const float* __restrict__ b,    // [D2*D3]
                              const float* __restrict__ root) // [D2, D3]
{
    int n = blockIdx.x;
    int cs = blockIdx.y;
    int tid = threadIdx.x;
    int ibase = cs*ICH3;
    __shared__ float4 sc[NN-1];
    __shared__ float  sx[NN*ICH3];
    if (tid < NN-1) {
        int k = tid, s = k + (k >= n);
        sc[k] = *reinterpret_cast<const float4*>(ea + edge_id(s, n)*4);
    }
    for (int idx = tid; idx < NN*ICH3; idx += 128) {
        int k = idx / ICH3, i = idx % ICH3;
        int s = (k < NN-1) ? (k + (k >= n)) : n;
        sx[idx] = g_h2[s*D2 + ibase + i];
    }
    __syncthreads();

    int o = tid;
    float acc = 0.f, r = 0.f;
    for (int i = 0; i < ICH3; i++) {
        int base = (ibase + i)*D3;
        float w0 = w[            base+o];
        float w1 = w[  D2*D3 +   base+o];
        float w2 = w[2*D2*D3 +   base+o];
        float w3 = w[3*D2*D3 +   base+o];
        float bb = b[base+o];
        float xn = sx[(NN-1)*ICH3 + i];
        r = fmaf(xn, root[base+o], r);
        #pragma unroll
        for (int k = 0; k < NN-1; k++) {
            float4 c = sc[k];
            float xv = sx[k*ICH3 + i];
            float t = fmaf(c.x, w0, fmaf(c.y, w1, fmaf(c.z, w2, fmaf(c.w, w3, bb))));
            acc = fmaf(xv, fmaxf(t, 0.f), acc);
        }
    }
    g_p3[cs][n*D3+o] = acc*(1.f/34.f) + r;
}

__global__ void fin3_kernel(const float* __restrict__ bias) {
    int idx = blockIdx.x*blockDim.x + threadIdx.x;
    if (idx >= NN*D3) return;
    float s = 0.f;
    #pragma unroll
    for (int p = 0; p < NS3; p++) s += g_p3[p][idx];
    g_h3[idx] = fmaxf(s + bias[idx % D3], 0.f);
}

// ---------------- CBT output ----------------
// block per row a; 4 warps cover the 35 columns, shfl-reduce over features
__global__ void cbt_kernel(float* __restrict__ out) {
    int a = blockIdx.x;
    int tid = threadIdx.x;  // 128
    __shared__ float sa[D3];
    sa[tid] = g_h3[a*D3 + tid];
    __syncthreads();
    int warp = tid >> 5, lane = tid & 31;
    for (int i = warp; i < NN; i += 4) {
        float s = 0.f;
        #pragma unroll
        for (int q = 0; q < 4; q++) {
            int f = lane + q*32;
            s += fabsf(g_h3[i*D3 + f] - sa[f]);
        }
        #pragma unroll
        for (int off = 16; off; off >>= 1)
            s += __shfl_down_sync(0xffffffffu, s, off);
        if (lane == 0) out[a*NN + i] = s;
    }
}

extern "C" void kernel_launch(void* const* d_in, const int* in_sizes, int n_in,
                              void* d_out, int out_size) {
    const float* x   = (const float*)d_in[0];
    const float* ea  = (const float*)d_in[1];
    // d_in[2] = edge_index (unused; structure derived analytically)
    const float* m1w = (const float*)d_in[3];
    const float* m1b = (const float*)d_in[4];
    const float* r1  = (const float*)d_in[5];
    const float* b1  = (const float*)d_in[6];
    const float* m2w = (const float*)d_in[7];
    const float* m2b = (const float*)d_in[8];
    const float* r2  = (const float*)d_in[9];
    const float* b2  = (const float*)d_in[10];
    const float* m3w = (const float*)d_in[11];
    const float* m3b = (const float*)d_in[12];
    const float* r3  = (const float*)d_in[13];
    const float* b3  = (const float*)d_in[14];
    float* out = (float*)d_out;

    layer1_kernel<<<NN, D1>>>(x, ea, m1w, m1b, r1, b1);
    l2edge_kernel<<<dim3(NN, NS2), 128>>>(ea, m2w, m2b, r2);
    fin2_kernel<<<(NN*D2 + 255)/256, 256>>>(b2);
    l3edge_kernel<<<dim3(NN, NS3), 128>>>(ea, m3w, m3b, r3);
    fin3_kernel<<<(NN*D3 + 127)/128, 128>>>(b3);
    cbt_kernel<<<NN, D3>>>(out);
}

// round 4
// speedup vs baseline: 1.0740x; 1.0740x over previous
#include <cuda_runtime.h>

#define NN   35
#define D1   512
#define D2   256
#define D3   128
#define NS2  16
#define ICH2 (D1/NS2)   // 32
#define NS3  16
#define ICH3 (D2/NS3)   // 16
#define KH   17         // edges per k-half (34/2)

typedef unsigned long long ull;

// scratch (no allocations allowed)
__device__ float g_h1[NN*D1];
__device__ float g_h2[NN*D2];
__device__ float g_h3[NN*D3];
__device__ float g_p2[NS2*2][NN*D2];
__device__ float g_p3[NS3*2][NN*D3];

// COO is src-major, fully connected, no self-loops:
// edge(s -> n) has id  s*(NN-1) + (s < n ? n-1 : n)
__device__ __forceinline__ int edge_id(int s, int n) {
    return s*(NN-1) + (s < n ? n-1 : n);
}

// ---- packed f32x2 helpers ----
__device__ __forceinline__ ull fma2(ull a, ull b, ull c) {
    ull d;
    asm("fma.rn.f32x2 %0, %1, %2, %3;" : "=l"(d) : "l"(a), "l"(b), "l"(c));
    return d;
}
__device__ __forceinline__ ull pk2(float lo, float hi) {
    ull r; asm("mov.b64 %0, {%1,%2};" : "=l"(r) : "f"(lo), "f"(hi)); return r;
}
__device__ __forceinline__ void upk2(ull v, float& lo, float& hi) {
    asm("mov.b64 {%0,%1}, %2;" : "=f"(lo), "=f"(hi) : "l"(v));
}
// relu on both halves: unpack is register-pair aliasing (free), FMNMX on ALU pipe
__device__ __forceinline__ ull relu2(ull t) {
    float lo, hi; upk2(t, lo, hi);
    return pk2(fmaxf(lo, 0.f), fmaxf(hi, 0.f));
}

// ---------------- Layer 1: in_c = 1 (tiny) ----------------
__global__ void layer1_kernel(const float* __restrict__ x,
                              const float* __restrict__ ea,
                              const float* __restrict__ w,
                              const float* __restrict__ b,
                              const float* __restrict__ root,
                              const float* __restrict__ bias) {
    int n = blockIdx.x;
    int o = threadIdx.x;          // 0..511
    __shared__ float4 sc[NN-1];
    __shared__ float  sxs[NN-1];
    if (o < NN-1) {
        int k = o;
        int s = k + (k >= n);
        sc[k]  = *reinterpret_cast<const float4*>(ea + edge_id(s, n)*4);
        sxs[k] = x[s];
    }
    __syncthreads();
    float w0 = w[o], w1 = w[D1+o], w2 = w[2*D1+o], w3 = w[3*D1+o];
    float bb = b[o];
    float acc = 0.f;
    #pragma unroll
    for (int k = 0; k < NN-1; k++) {
        float4 c = sc[k];
        float t = fmaf(c.x, w0, fmaf(c.y, w1, fmaf(c.z, w2, fmaf(c.w, w3, bb))));
        acc = fmaf(sxs[k], fmaxf(t, 0.f), acc);
    }
    float v = acc * (1.f/34.f) + x[n]*root[o] + bias[o];
    g_h1[n*D1+o] = fmaxf(v, 0.f);
}

// ---------------- Layer 2 edge/message kernel ----------------
// grid (NN, NS2, 2), 128 threads; thread owns output pair (2*tid, 2*tid+1)
__global__ void l2edge_kernel(const float* __restrict__ ea,
                              const float* __restrict__ w,    // [4, D1*D2]
                              const float* __restrict__ b,    // [D1*D2]
                              const float* __restrict__ root) // [D1, D2]
{
    int n  = blockIdx.x;
    int cs = blockIdx.y;
    int kh = blockIdx.z;
    int tid = threadIdx.x;
    int k0 = kh*KH;
    int ibase = cs*ICH2;

    __shared__ ulonglong2 scp[KH][2];        // (cx,cx),(cy,cy) | (cz,cz),(cw,cw)
    __shared__ ull        sx2[(KH+1)*ICH2];  // (v,v) pairs; slot KH = node n itself

    if (tid < KH) {
        int k = k0 + tid;
        int s = k + (k >= n);
        float4 c = *reinterpret_cast<const float4*>(ea + edge_id(s, n)*4);
        *reinterpret_cast<float4*>(&scp[tid][0]) = make_float4(c.x, c.x, c.y, c.y);
        *reinterpret_cast<float4*>(&scp[tid][1]) = make_float4(c.z, c.z, c.w, c.w);
    }
    for (int idx = tid; idx < (KH+1)*ICH2; idx += 128) {
        int kk = idx / ICH2, i = idx % ICH2;
        int s = (kk < KH) ? (k0 + kk + (k0 + kk >= n)) : n;
        float v = g_h1[s*D1 + ibase + i];
        sx2[idx] = pk2(v, v);
    }
    __syncthreads();

    const ull* wq = reinterpret_cast<const ull*>(w);
    const ull* bq = reinterpret_cast<const ull*>(b);
    const ull* rq = reinterpret_cast<const ull*>(root);
    const int PL = D1*D2/2;   // ull elements per weight plane

    ull acc = 0ull, racc = 0ull;

    // prefetch i = 0
    int base0 = (ibase + 0)*(D2/2) + tid;
    ull cw0 = wq[base0], cw1 = wq[base0 + PL], cw2 = wq[base0 + 2*PL], cw3 = wq[base0 + 3*PL];
    ull cb  = bq[base0];
    ull cr  = rq[base0];

    for (int i = 0; i < ICH2; i++) {
        int inx = (i + 1 < ICH2) ? i + 1 : i;
        int basen = (ibase + inx)*(D2/2) + tid;
        ull nw0 = wq[basen], nw1 = wq[basen + PL], nw2 = wq[basen + 2*PL], nw3 = wq[basen + 3*PL];
        ull nb  = bq[basen];
        ull nr  = rq[basen];

        if (kh == 0) racc = fma2(sx2[KH*ICH2 + i], cr, racc);
        #pragma unroll
        for (int k = 0; k < KH; k++) {
            ulonglong2 p0 = scp[k][0];
            ulonglong2 p1 = scp[k][1];
            ull t = fma2(p0.x, cw0, cb);
            t = fma2(p0.y, cw1, t);
            t = fma2(p1.x, cw2, t);
            t = fma2(p1.y, cw3, t);
            t = relu2(t);
            acc = fma2(sx2[k*ICH2 + i], t, acc);
        }
        cw0 = nw0; cw1 = nw1; cw2 = nw2; cw3 = nw3; cb = nb; cr = nr;
    }

    float alo, ahi, rlo, rhi;
    upk2(acc, alo, ahi);
    upk2(racc, rlo, rhi);
    float2 res = make_float2(alo*(1.f/34.f) + rlo, ahi*(1.f/34.f) + rhi);
    reinterpret_cast<float2*>(&g_p2[cs*2 + kh][n*D2])[tid] = res;
}

__global__ void fin2_kernel(const float* __restrict__ bias) {
    int idx = blockIdx.x*blockDim.x + threadIdx.x;
    if (idx >= NN*D2) return;
    float s = 0.f;
    #pragma unroll
    for (int p = 0; p < NS2*2; p++) s += g_p2[p][idx];
    g_h2[idx] = fmaxf(s + bias[idx % D2], 0.f);
}

// ---------------- Layer 3 edge/message kernel ----------------
// grid (NN, NS3, 2), 128 threads; thread owns output o = tid, packs i-pairs
__global__ void l3edge_kernel(const float* __restrict__ ea,
                              const float* __restrict__ w,    // [4, D2*D3]
                              const float* __restrict__ b,    // [D2*D3]
                              const float* __restrict__ root) // [D2, D3]
{
    int n  = blockIdx.x;
    int cs = blockIdx.y;
    int kh = blockIdx.z;
    int tid = threadIdx.x;   // = o
    int k0 = kh*KH;
    int ibase = cs*ICH3;

    __shared__ ulonglong2 scp[KH][2];
    __shared__ float      sx[(KH+1)*ICH3];

    if (tid < KH) {
        int k = k0 + tid;
        int s = k + (k >= n);
        float4 c = *reinterpret_cast<const float4*>(ea + edge_id(s, n)*4);
        *reinterpret_cast<float4*>(&scp[tid][0]) = make_float4(c.x, c.x, c.y, c.y);
        *reinterpret_cast<float4*>(&scp[tid][1]) = make_float4(c.z, c.z, c.w, c.w);
    }
    for (int idx = tid; idx < (KH+1)*ICH3; idx += 128) {
        int kk = idx / ICH3, i = idx % ICH3;
        int s = (kk < KH) ? (k0 + kk + (k0 + kk >= n)) : n;
        sx[idx] = g_h2[s*D2 + ibase + i];
    }
    __syncthreads();

    const int PL = D2*D3;
    ull acc = 0ull, racc = 0ull;

    // weight pair for i-pair ip: halves are (i=2ip) and (i=2ip+1), stride D3 apart
    auto ldw = [&](const float* __restrict__ p, int i) -> ull {
        int a = (ibase + i)*D3 + tid;
        return pk2(p[a], p[a + D3]);
    };

    // prefetch ip = 0
    ull cw0 = ldw(w, 0), cw1 = ldw(w + PL, 0), cw2 = ldw(w + 2*PL, 0), cw3 = ldw(w + 3*PL, 0);
    ull cb  = ldw(b, 0);
    ull cr  = ldw(root, 0);

    #pragma unroll 2
    for (int ip = 0; ip < ICH3/2; ip++) {
        int i  = 2*ip;
        int inx = (ip + 1 < ICH3/2) ? i + 2 : i;
        ull nw0 = ldw(w, inx), nw1 = ldw(w + PL, inx), nw2 = ldw(w + 2*PL, inx), nw3 = ldw(w + 3*PL, inx);
        ull nb  = ldw(b, inx);
        ull nr  = ldw(root, inx);

        if (kh == 0) {
            ull xn2 = *reinterpret_cast<const ull*>(&sx[KH*ICH3 + i]);
            racc = fma2(xn2, cr, racc);
        }
        #pragma unroll
        for (int k = 0; k < KH; k++) {
            ulonglong2 p0 = scp[k][0];
            ulonglong2 p1 = scp[k][1];
            ull t = fma2(p0.x, cw0, cb);
            t = fma2(p0.y, cw1, t);
            t = fma2(p1.x, cw2, t);
            t = fma2(p1.y, cw3, t);
            t = relu2(t);
            ull xv2 = *reinterpret_cast<const ull*>(&sx[k*ICH3 + i]);
            acc = fma2(xv2, t, acc);
        }
        cw0 = nw0; cw1 = nw1; cw2 = nw2; cw3 = nw3; cb = nb; cr = nr;
    }

    float alo, ahi, rlo, rhi;
    upk2(acc, alo, ahi);
    upk2(racc, rlo, rhi);
    g_p3[cs*2 + kh][n*D3 + tid] = (alo + ahi)*(1.f/34.f) + (rlo + rhi);
}

__global__ void fin3_kernel(const float* __restrict__ bias) {
    int idx = blockIdx.x*blockDim.x + threadIdx.x;
    if (idx >= NN*D3) return;
    float s = 0.f;
    #pragma unroll
    for (int p = 0; p < NS3*2; p++) s += g_p3[p][idx];
    g_h3[idx] = fmaxf(s + bias[idx % D3], 0.f);
}

// ---------------- CBT output ----------------
__global__ void cbt_kernel(float* __restrict__ out) {
    int a = blockIdx.x;
    int tid = threadIdx.x;  // 128
    __shared__ float sa[D3];
    sa[tid] = g_h3[a*D3 + tid];
    __syncthreads();
    int warp = tid >> 5, lane = tid & 31;
    for (int i = warp; i < NN; i += 4) {
        float s = 0.f;
        #pragma unroll
        for (int q = 0; q < 4; q++) {
            int f = lane + q*32;
            s += fabsf(g_h3[i*D3 + f] - sa[f]);
        }
        #pragma unroll
        for (int off = 16; off; off >>= 1)
            s += __shfl_down_sync(0xffffffffu, s, off);
        if (lane == 0) out[a*NN + i] = s;
    }
}

extern "C" void kernel_launch(void* const* d_in, const int* in_sizes, int n_in,
                              void* d_out, int out_size) {
    const float* x   = (const float*)d_in[0];
    const float* ea  = (const float*)d_in[1];
    // d_in[2] = edge_index (unused; structure derived analytically)
    const float* m1w = (const float*)d_in[3];
    const float* m1b = (const float*)d_in[4];
    const float* r1  = (const float*)d_in[5];
    const float* b1  = (const float*)d_in[6];
    const float* m2w = (const float*)d_in[7];
    const float* m2b = (const float*)d_in[8];
    const float* r2  = (const float*)d_in[9];
    const float* b2  = (const float*)d_in[10];
    const float* m3w = (const float*)d_in[11];
    const float* m3b = (const float*)d_in[12];
    const float* r3  = (const float*)d_in[13];
    const float* b3  = (const float*)d_in[14];
    float* out = (float*)d_out;

    layer1_kernel<<<NN, D1>>>(x, ea, m1w, m1b, r1, b1);
    l2edge_kernel<<<dim3(NN, NS2, 2), 128>>>(ea, m2w, m2b, r2);
    fin2_kernel<<<(NN*D2 + 255)/256, 256>>>(b2);
    l3edge_kernel<<<dim3(NN, NS3, 2), 128>>>(ea, m3w, m3b, r3);
    fin3_kernel<<<(NN*D3 + 127)/128, 128>>>(b3);
    cbt_kernel<<<NN, D3>>>(out);
}